// round 11
// baseline (speedup 1.0000x reference)
#include <cuda_runtime.h>
#include <cuda_bf16.h>
#include <math.h>

#define H       1024
#define DIN     512
#define T_STEPS 512
#define BATCH   32
#define DT_C    0.1f

#define GRID_R  128
#define BLOCK_R 384
#define HB      8      // H / GRID_R

typedef unsigned long long u64;

// ---------------- f32x2 packed math (Blackwell) ----------------
__device__ __forceinline__ u64 fma2(u64 a, u64 b, u64 c) {
    u64 d;
    asm("fma.rn.f32x2 %0, %1, %2, %3;" : "=l"(d) : "l"(a), "l"(b), "l"(c));
    return d;
}
__device__ __forceinline__ u64 add2(u64 a, u64 b) {
    u64 d;
    asm("add.rn.f32x2 %0, %1, %2;" : "=l"(d) : "l"(a), "l"(b));
    return d;
}
__device__ __forceinline__ u64 dup2(float a) {
    u64 d;
    asm("mov.b64 %0, {%1, %1};" : "=l"(d) : "f"(a));
    return d;
}
__device__ __forceinline__ u64 dup2u(unsigned a) {
    u64 d;
    asm("mov.b64 %0, {%1, %1};" : "=l"(d) : "r"(a));
    return d;
}
// bf16 pair decode: u32 (two bf16) -> two f32 bit patterns via PRMT (exact)
__device__ __forceinline__ unsigned bf_lo(unsigned x) {
    unsigned r;
    asm("prmt.b32 %0, %1, %2, 0x1044;" : "=r"(r) : "r"(x), "r"(0u));
    return r;
}
__device__ __forceinline__ unsigned bf_hi(unsigned x) {
    unsigned r;
    asm("prmt.b32 %0, %1, %2, 0x3244;" : "=r"(r) : "r"(x), "r"(0u));
    return r;
}
__device__ __forceinline__ float tanh_fast(float x) {
    float e = __expf(2.0f * x);
    return 1.0f - __fdividef(2.0f, e + 1.0f);
}
__device__ __forceinline__ float sigmoid_fast(float x) {
    return __fdividef(1.0f, 1.0f + __expf(-x));
}

// ---------------- device scratch (static, allocation-free) ----------------
__device__ float g_Wr[H * H];
__device__ float g_Wi[H * H];
__device__ float g_Ux[T_STEPS * BATCH * H];
__device__ float g_ZR[T_STEPS * BATCH * H];
__device__ __nv_bfloat16 g_act[2 * 3 * H * BATCH];   // [buf][mat][k][b], bf16
__device__ unsigned g_bar_count;
__device__ unsigned g_bar_gen;

// ---------------- grid-wide barrier (all CTAs resident) ----------------
__device__ __forceinline__ void grid_barrier() {
    __syncthreads();
    if (threadIdx.x == 0) {
        unsigned gen = *(volatile unsigned*)&g_bar_gen;
        __threadfence();
        unsigned t = atomicAdd(&g_bar_count, 1u);
        if (t == GRID_R - 1) {
            g_bar_count = 0u;
            __threadfence();
            atomicAdd(&g_bar_gen, 1u);
        } else {
            while (*(volatile unsigned*)&g_bar_gen == gen) { }
        }
        __threadfence();
    }
    __syncthreads();
}

// ---------------- prep: masked weights ----------------
__global__ void prep_kernel(const float* __restrict__ Wr_w, const float* __restrict__ mask_r,
                            const float* __restrict__ Wi_w, const float* __restrict__ mask_i) {
    int i = blockIdx.x * blockDim.x + threadIdx.x;
    if (i < H * H) {
        g_Wr[i] = Wr_w[i] * (1.0f / (1.0f + expf(-mask_r[i])));
        g_Wi[i] = Wi_w[i] * (1.0f / (1.0f + expf(-mask_i[i])));
    }
}

__global__ void init_kernel() {
    int i = blockIdx.x * blockDim.x + threadIdx.x;
    if (i < 2 * 3 * H * BATCH) g_act[i] = __float2bfloat16(0.0f);
}

// ---------------- fp32 GEMM (f32x2 inner): C = A * B^T + bias ----------------
#define GBM 128
#define GBN 128
#define GBK 8
__global__ __launch_bounds__(256) void sgemm_abt(
    const float* __restrict__ A, const float* __restrict__ B,
    const float* __restrict__ bias, float* __restrict__ C,
    int M, int N, int K) {
    __shared__ float As[GBK][GBM];
    __shared__ float Bs[GBK][GBN];
    const int tid = threadIdx.x;
    const int bm = blockIdx.y * GBM;
    const int bn = blockIdx.x * GBN;
    const int lr = tid >> 1;
    const int lc = (tid & 1) * 4;
    const int tx = tid & 15;
    const int ty = tid >> 4;

    u64 acc2[8][4];
#pragma unroll
    for (int i = 0; i < 8; i++)
#pragma unroll
        for (int j = 0; j < 4; j++) acc2[i][j] = 0ull;

    const float* Ap = A + (long)(bm + lr) * K + lc;
    const float* Bp = B + (long)(bn + lr) * K + lc;
    float4 a4 = *(const float4*)Ap;
    float4 b4 = *(const float4*)Bp;

    for (int k0 = 0; k0 < K; k0 += GBK) {
        As[lc + 0][lr] = a4.x; As[lc + 1][lr] = a4.y;
        As[lc + 2][lr] = a4.z; As[lc + 3][lr] = a4.w;
        Bs[lc + 0][lr] = b4.x; Bs[lc + 1][lr] = b4.y;
        Bs[lc + 2][lr] = b4.z; Bs[lc + 3][lr] = b4.w;
        __syncthreads();
        if (k0 + GBK < K) {
            a4 = *(const float4*)(Ap + k0 + GBK);
            b4 = *(const float4*)(Bp + k0 + GBK);
        }
#pragma unroll
        for (int kk = 0; kk < GBK; kk++) {
            float4 a0 = *(const float4*)&As[kk][ty * 8];
            float4 a1 = *(const float4*)&As[kk][ty * 8 + 4];
            ulonglong2 bp0 = *(const ulonglong2*)&Bs[kk][tx * 8];
            ulonglong2 bp1 = *(const ulonglong2*)&Bs[kk][tx * 8 + 4];
            u64 ad[8] = {dup2(a0.x), dup2(a0.y), dup2(a0.z), dup2(a0.w),
                         dup2(a1.x), dup2(a1.y), dup2(a1.z), dup2(a1.w)};
#pragma unroll
            for (int i = 0; i < 8; i++) {
                acc2[i][0] = fma2(ad[i], bp0.x, acc2[i][0]);
                acc2[i][1] = fma2(ad[i], bp0.y, acc2[i][1]);
                acc2[i][2] = fma2(ad[i], bp1.x, acc2[i][2]);
                acc2[i][3] = fma2(ad[i], bp1.y, acc2[i][3]);
            }
        }
        __syncthreads();
    }

#pragma unroll
    for (int i = 0; i < 8; i++) {
        long row = bm + ty * 8 + i;
#pragma unroll
        for (int j = 0; j < 4; j++) {
            int col = bn + tx * 8 + j * 2;
            float2 v = *(float2*)&acc2[i][j];
            v.x += bias[col];
            v.y += bias[col + 1];
            *(float2*)&C[row * N + col] = v;
        }
    }
}

// ---------------- persistent recurrence kernel ----------------
// 384 threads = 3 mats x 32 ks x 4 bq(8 batches each); warp = 8 ks x 4 bq.
// Each thread: 8 rows (4 f32x2 row-pairs) x 8 batches = 32 accumulators; 32 k-iters.
// Per iter: 1 LDG.128 (8 bf16 acts) + 2 LDS.128 (8 fp32 row-weights) + 16 ALU + 32 fma2.
struct RecSmem {
    float W[3][H][HB];           // [mat][k][row], fp32 (96KB)
    u64   red[3][4][4][32];      // warp-reduced partials [m][ksgrp][bq][rp*8+b] (12KB)
    float res[3][HB][BATCH];
    __nv_bfloat16 acth[3][HB][BATCH];   // staged bf16 act planes (1.5KB)
    float wb[3][HB];
    float br[HB], bi[HB], tb[HB];
};

__global__ void __launch_bounds__(BLOCK_R, 1) rec_kernel(
    const float* __restrict__ Wt_w,
    const float* __restrict__ Wr_b, const float* __restrict__ Wi_b,
    const float* __restrict__ Wt_b, const float* __restrict__ b_real,
    const float* __restrict__ b_imag, const float* __restrict__ tau_bias) {
    extern __shared__ char smem_raw[];
    RecSmem& sm = *reinterpret_cast<RecSmem*>(smem_raw);
    const int tid = threadIdx.x;
    const int hbase = blockIdx.x * HB;

    // ---- load weights into SMEM [mat][k][row] (resident for all 512 steps) ----
    for (int idx = tid; idx < 3 * HB * H; idx += BLOCK_R) {
        int m   = idx >> 13;
        int rem = idx & 8191;
        int r   = rem >> 10;
        int k   = rem & 1023;
        float w;
        if (m == 0)      w = g_Wr[(long)(hbase + r) * H + k];
        else if (m == 1) w = g_Wi[(long)(hbase + r) * H + k];
        else             w = Wt_w[(long)(hbase + r) * H + k];
        sm.W[m][k][r] = w;
    }
    if (tid < HB) {
        sm.wb[0][tid] = Wr_b[hbase + tid];
        sm.wb[1][tid] = Wi_b[hbase + tid];
        sm.wb[2][tid] = Wt_b[hbase + tid];
        sm.br[tid] = b_real[hbase + tid];
        sm.bi[tid] = b_imag[hbase + tid];
        sm.tb[tid] = tau_bias[hbase + tid];
    }
    __syncthreads();

    const int m  = tid >> 7;          // 0..2
    const int r5 = tid & 127;
    const int ks = r5 >> 2;           // 0..31
    const int bq = r5 & 3;            // 0..3 (8 batches each)

    const char* wk_base = (const char*)&sm.W[m][0][0];

    // cell state held in registers for the whole sequence (CTA-private)
    const int cb  = tid >> 3;         // batch (valid when tid < 256)
    const int chl = tid & 7;          // local h
    float zr = 0.0f, zi = 0.0f;

    int cur = 0;
    for (int t = 0; t < T_STEPS; t++) {
        // prefetch Ux for the epilogue (overlaps with matmul)
        float ux = 0.0f;
        if (tid < HB * BATCH)
            ux = __ldg(&g_Ux[((long)t * BATCH + cb) * H + hbase + chl]);

        const __nv_bfloat16* actp =
            g_act + (size_t)(cur * 3 + m) * (H * BATCH) + bq * 8;

        // acc[rp*8 + b]: f32x2 = rows (2rp, 2rp+1), batch (bq*8 + b)
        u64 acc[32];
#pragma unroll
        for (int j = 0; j < 32; j++) acc[j] = 0ull;

#pragma unroll 2
        for (int i = 0; i < 32; i++) {
            int k = ks + (i << 5);
            uint4 a = __ldg((const uint4*)(actp + k * BATCH));
            ulonglong2 wA = *(const ulonglong2*)(wk_base + (size_t)k * (HB * 4));
            ulonglong2 wB = *(const ulonglong2*)(wk_base + (size_t)k * (HB * 4) + 16);
            u64 ad0 = dup2u(bf_lo(a.x));
            u64 ad1 = dup2u(bf_hi(a.x));
            u64 ad2 = dup2u(bf_lo(a.y));
            u64 ad3 = dup2u(bf_hi(a.y));
            u64 ad4 = dup2u(bf_lo(a.z));
            u64 ad5 = dup2u(bf_hi(a.z));
            u64 ad6 = dup2u(bf_lo(a.w));
            u64 ad7 = dup2u(bf_hi(a.w));
            acc[0]  = fma2(ad0, wA.x, acc[0]);
            acc[1]  = fma2(ad1, wA.x, acc[1]);
            acc[2]  = fma2(ad2, wA.x, acc[2]);
            acc[3]  = fma2(ad3, wA.x, acc[3]);
            acc[4]  = fma2(ad4, wA.x, acc[4]);
            acc[5]  = fma2(ad5, wA.x, acc[5]);
            acc[6]  = fma2(ad6, wA.x, acc[6]);
            acc[7]  = fma2(ad7, wA.x, acc[7]);
            acc[8]  = fma2(ad0, wA.y, acc[8]);
            acc[9]  = fma2(ad1, wA.y, acc[9]);
            acc[10] = fma2(ad2, wA.y, acc[10]);
            acc[11] = fma2(ad3, wA.y, acc[11]);
            acc[12] = fma2(ad4, wA.y, acc[12]);
            acc[13] = fma2(ad5, wA.y, acc[13]);
            acc[14] = fma2(ad6, wA.y, acc[14]);
            acc[15] = fma2(ad7, wA.y, acc[15]);
            acc[16] = fma2(ad0, wB.x, acc[16]);
            acc[17] = fma2(ad1, wB.x, acc[17]);
            acc[18] = fma2(ad2, wB.x, acc[18]);
            acc[19] = fma2(ad3, wB.x, acc[19]);
            acc[20] = fma2(ad4, wB.x, acc[20]);
            acc[21] = fma2(ad5, wB.x, acc[21]);
            acc[22] = fma2(ad6, wB.x, acc[22]);
            acc[23] = fma2(ad7, wB.x, acc[23]);
            acc[24] = fma2(ad0, wB.y, acc[24]);
            acc[25] = fma2(ad1, wB.y, acc[25]);
            acc[26] = fma2(ad2, wB.y, acc[26]);
            acc[27] = fma2(ad3, wB.y, acc[27]);
            acc[28] = fma2(ad4, wB.y, acc[28]);
            acc[29] = fma2(ad5, wB.y, acc[29]);
            acc[30] = fma2(ad6, wB.y, acc[30]);
            acc[31] = fma2(ad7, wB.y, acc[31]);
        }

        // warp butterfly over the 8 ks lanes (lane^4, lane^8, lane^16)
#pragma unroll
        for (int j = 0; j < 32; j++) {
            acc[j] = add2(acc[j], __shfl_xor_sync(0xffffffffu, acc[j], 4));
            acc[j] = add2(acc[j], __shfl_xor_sync(0xffffffffu, acc[j], 8));
            acc[j] = add2(acc[j], __shfl_xor_sync(0xffffffffu, acc[j], 16));
        }
        if ((ks & 7) == 0) {
            int ksg = ks >> 3;      // warp index within m: 0..3
#pragma unroll
            for (int j = 0; j < 32; j++) sm.red[m][ksg][bq][j] = acc[j];
        }
        __syncthreads();

        // combine 4 k-groups: 384 combos (m, rp, b_abs), one per thread
        {
            int m2  = tid >> 7;
            int rem = tid & 127;
            int rp  = rem >> 5;       // row pair 0..3
            int ba  = rem & 31;       // absolute batch
            int jj  = rp * 8 + (ba & 7);
            int bq2 = ba >> 3;
            float2 s = *(float2*)&sm.red[m2][0][bq2][jj];
#pragma unroll
            for (int g = 1; g < 4; g++) {
                float2 p = *(float2*)&sm.red[m2][g][bq2][jj];
                s.x += p.x; s.y += p.y;
            }
            sm.res[m2][rp * 2 + 0][ba] = s.x;
            sm.res[m2][rp * 2 + 1][ba] = s.y;
        }
        __syncthreads();

        // elementwise update (state in registers), stage bf16 act planes in SMEM
        if (tid < HB * BATCH) {
            int b  = cb;
            int hl = chl;
            int h  = hbase + hl;
            float wr = sm.res[0][hl][b] + sm.wb[0][hl];
            float wi = sm.res[1][hl][b] + sm.wb[1][hl];
            float wt = sm.res[2][hl][b] + sm.wb[2][hl];
            float dr = -zr + wr + ux + sm.br[hl];
            float di = -zi + wi + ux + sm.bi[hl];
            float tau = sigmoid_fast(wt) + sm.tb[hl];
            tau = fminf(fmaxf(tau, 0.01f), 1.0f) + 1e-6f;
            float rtau = __fdividef(1.0f, tau);
            dr = fminf(fmaxf(dr * rtau, -10.0f), 10.0f);
            di = fminf(fmaxf(di * rtau, -10.0f), 10.0f);
            zr = fminf(fmaxf(zr + DT_C * dr, -100.0f), 100.0f);
            zi = fminf(fmaxf(zi + DT_C * di, -100.0f), 100.0f);
            g_ZR[((long)t * BATCH + b) * H + h] = zr;
            sm.acth[0][hl][b] = __float2bfloat16(tanh_fast(zr));
            sm.acth[1][hl][b] = __float2bfloat16(tanh_fast(zi));
            sm.acth[2][hl][b] = __float2bfloat16(sqrtf(zr * zr + zi * zi));
        }
        __syncthreads();

        // coalesced store of the 3 bf16 act planes (96 x STG.128)
        const int nxt = cur ^ 1;
        if (tid < 96) {
            int p   = tid >> 5;
            int off = (tid & 31) * 16;  // bytes
            float4 v = *(float4*)((const char*)&sm.acth[p][0][0] + off);
            *(float4*)((char*)(g_act + ((size_t)(nxt * 3 + p) * H + hbase) * BATCH) + off) = v;
        }

        grid_barrier();
        cur ^= 1;
    }
}

// ---------------- launch ----------------
extern "C" void kernel_launch(void* const* d_in, const int* in_sizes, int n_in,
                              void* d_out, int out_size) {
    const float* x_seq    = (const float*)d_in[0];
    const float* Wr_w     = (const float*)d_in[1];
    const float* Wr_b     = (const float*)d_in[2];
    const float* Wi_w     = (const float*)d_in[3];
    const float* Wi_b     = (const float*)d_in[4];
    const float* U_w      = (const float*)d_in[5];
    const float* U_b      = (const float*)d_in[6];
    const float* Wt_w     = (const float*)d_in[7];
    const float* Wt_b     = (const float*)d_in[8];
    const float* b_real   = (const float*)d_in[9];
    const float* b_imag   = (const float*)d_in[10];
    const float* mask_r   = (const float*)d_in[11];
    const float* mask_i   = (const float*)d_in[12];
    const float* tau_bias = (const float*)d_in[13];
    const float* out_w    = (const float*)d_in[14];
    const float* out_b    = (const float*)d_in[15];
    float* y = (float*)d_out;

    float *p_Ux = nullptr, *p_ZR = nullptr;
    cudaGetSymbolAddress((void**)&p_Ux, g_Ux);
    cudaGetSymbolAddress((void**)&p_ZR, g_ZR);

    prep_kernel<<<(H * H + 255) / 256, 256>>>(Wr_w, mask_r, Wi_w, mask_i);
    init_kernel<<<(2 * 3 * H * BATCH + 255) / 256, 256>>>();

    {
        dim3 grid(H / GBN, (T_STEPS * BATCH) / GBM);
        sgemm_abt<<<grid, 256>>>(x_seq, U_w, U_b, p_Ux, T_STEPS * BATCH, H, DIN);
    }

    {
        int smem = (int)sizeof(RecSmem);
        cudaFuncSetAttribute(rec_kernel, cudaFuncAttributeMaxDynamicSharedMemorySize, smem);
        rec_kernel<<<GRID_R, BLOCK_R, smem>>>(Wt_w, Wr_b, Wi_b, Wt_b, b_real, b_imag, tau_bias);
    }

    {
        dim3 grid(H / GBN, (T_STEPS * BATCH) / GBM);
        sgemm_abt<<<grid, 256>>>(p_ZR, out_w, out_b, y, T_STEPS * BATCH, H, H);
    }
}

// round 12
// speedup vs baseline: 1.1329x; 1.1329x over previous
#include <cuda_runtime.h>
#include <cuda_bf16.h>
#include <math.h>

#define H       1024
#define DIN     512
#define T_STEPS 512
#define BATCH   32
#define DT_C    0.1f

#define GRID_R  128
#define BLOCK_R 768
#define HB      8      // H / GRID_R

typedef unsigned long long u64;

// ---------------- f32x2 packed math (Blackwell) ----------------
__device__ __forceinline__ u64 fma2(u64 a, u64 b, u64 c) {
    u64 d;
    asm("fma.rn.f32x2 %0, %1, %2, %3;" : "=l"(d) : "l"(a), "l"(b), "l"(c));
    return d;
}
__device__ __forceinline__ u64 add2(u64 a, u64 b) {
    u64 d;
    asm("add.rn.f32x2 %0, %1, %2;" : "=l"(d) : "l"(a), "l"(b));
    return d;
}
__device__ __forceinline__ u64 dup2(float a) {
    u64 d;
    asm("mov.b64 %0, {%1, %1};" : "=l"(d) : "f"(a));
    return d;
}
__device__ __forceinline__ u64 dup2u(unsigned a) {
    u64 d;
    asm("mov.b64 %0, {%1, %1};" : "=l"(d) : "r"(a));
    return d;
}
// bf16 pair decode: u32 (two bf16) -> two f32 bit patterns via PRMT (exact)
__device__ __forceinline__ unsigned bf_lo(unsigned x) {
    unsigned r;
    asm("prmt.b32 %0, %1, %2, 0x1044;" : "=r"(r) : "r"(x), "r"(0u));
    return r;
}
__device__ __forceinline__ unsigned bf_hi(unsigned x) {
    unsigned r;
    asm("prmt.b32 %0, %1, %2, 0x3244;" : "=r"(r) : "r"(x), "r"(0u));
    return r;
}
__device__ __forceinline__ float tanh_fast(float x) {
    float e = __expf(2.0f * x);
    return 1.0f - __fdividef(2.0f, e + 1.0f);
}
__device__ __forceinline__ float sigmoid_fast(float x) {
    return __fdividef(1.0f, 1.0f + __expf(-x));
}

// ---------------- device scratch (static, allocation-free) ----------------
__device__ float g_Wr[H * H];
__device__ float g_Wi[H * H];
__device__ float g_Ux[T_STEPS * BATCH * H];
__device__ float g_ZR[T_STEPS * BATCH * H];
__device__ __nv_bfloat16 g_act[2 * 3 * H * BATCH];   // [buf][mat][k][b], bf16
__device__ unsigned g_bar_count;
__device__ unsigned g_bar_gen;

// ---------------- grid-wide barrier (all CTAs resident) ----------------
__device__ __forceinline__ void grid_barrier() {
    __syncthreads();
    if (threadIdx.x == 0) {
        unsigned gen = *(volatile unsigned*)&g_bar_gen;
        __threadfence();
        unsigned t = atomicAdd(&g_bar_count, 1u);
        if (t == GRID_R - 1) {
            g_bar_count = 0u;
            __threadfence();
            atomicAdd(&g_bar_gen, 1u);
        } else {
            while (*(volatile unsigned*)&g_bar_gen == gen) { }
        }
        __threadfence();
    }
    __syncthreads();
}

// ---------------- prep: masked weights ----------------
__global__ void prep_kernel(const float* __restrict__ Wr_w, const float* __restrict__ mask_r,
                            const float* __restrict__ Wi_w, const float* __restrict__ mask_i) {
    int i = blockIdx.x * blockDim.x + threadIdx.x;
    if (i < H * H) {
        g_Wr[i] = Wr_w[i] * (1.0f / (1.0f + expf(-mask_r[i])));
        g_Wi[i] = Wi_w[i] * (1.0f / (1.0f + expf(-mask_i[i])));
    }
}

__global__ void init_kernel() {
    int i = blockIdx.x * blockDim.x + threadIdx.x;
    if (i < 2 * 3 * H * BATCH) g_act[i] = __float2bfloat16(0.0f);
}

// ---------------- fp32 GEMM (f32x2 inner): C = A * B^T + bias ----------------
#define GBM 128
#define GBN 128
#define GBK 8
__global__ __launch_bounds__(256) void sgemm_abt(
    const float* __restrict__ A, const float* __restrict__ B,
    const float* __restrict__ bias, float* __restrict__ C,
    int M, int N, int K) {
    __shared__ float As[GBK][GBM];
    __shared__ float Bs[GBK][GBN];
    const int tid = threadIdx.x;
    const int bm = blockIdx.y * GBM;
    const int bn = blockIdx.x * GBN;
    const int lr = tid >> 1;
    const int lc = (tid & 1) * 4;
    const int tx = tid & 15;
    const int ty = tid >> 4;

    u64 acc2[8][4];
#pragma unroll
    for (int i = 0; i < 8; i++)
#pragma unroll
        for (int j = 0; j < 4; j++) acc2[i][j] = 0ull;

    const float* Ap = A + (long)(bm + lr) * K + lc;
    const float* Bp = B + (long)(bn + lr) * K + lc;
    float4 a4 = *(const float4*)Ap;
    float4 b4 = *(const float4*)Bp;

    for (int k0 = 0; k0 < K; k0 += GBK) {
        As[lc + 0][lr] = a4.x; As[lc + 1][lr] = a4.y;
        As[lc + 2][lr] = a4.z; As[lc + 3][lr] = a4.w;
        Bs[lc + 0][lr] = b4.x; Bs[lc + 1][lr] = b4.y;
        Bs[lc + 2][lr] = b4.z; Bs[lc + 3][lr] = b4.w;
        __syncthreads();
        if (k0 + GBK < K) {
            a4 = *(const float4*)(Ap + k0 + GBK);
            b4 = *(const float4*)(Bp + k0 + GBK);
        }
#pragma unroll
        for (int kk = 0; kk < GBK; kk++) {
            float4 a0 = *(const float4*)&As[kk][ty * 8];
            float4 a1 = *(const float4*)&As[kk][ty * 8 + 4];
            ulonglong2 bp0 = *(const ulonglong2*)&Bs[kk][tx * 8];
            ulonglong2 bp1 = *(const ulonglong2*)&Bs[kk][tx * 8 + 4];
            u64 ad[8] = {dup2(a0.x), dup2(a0.y), dup2(a0.z), dup2(a0.w),
                         dup2(a1.x), dup2(a1.y), dup2(a1.z), dup2(a1.w)};
#pragma unroll
            for (int i = 0; i < 8; i++) {
                acc2[i][0] = fma2(ad[i], bp0.x, acc2[i][0]);
                acc2[i][1] = fma2(ad[i], bp0.y, acc2[i][1]);
                acc2[i][2] = fma2(ad[i], bp1.x, acc2[i][2]);
                acc2[i][3] = fma2(ad[i], bp1.y, acc2[i][3]);
            }
        }
        __syncthreads();
    }

#pragma unroll
    for (int i = 0; i < 8; i++) {
        long row = bm + ty * 8 + i;
#pragma unroll
        for (int j = 0; j < 4; j++) {
            int col = bn + tx * 8 + j * 2;
            float2 v = *(float2*)&acc2[i][j];
            v.x += bias[col];
            v.y += bias[col + 1];
            *(float2*)&C[row * N + col] = v;
        }
    }
}

// ---------------- persistent recurrence kernel ----------------
// 768 threads = 3 mats x 32 ks x 8 bq; warp = 4 ks x 8 bq (R10 structure).
// Mainloop: act LDG software-pipelined by 1 iter; bf16 act decode via PRMT.
// Tail: update threads reduce directly from red (no combine phase / res array).
struct RecSmem {
    float W[3][H][HB];           // [mat][k][row], fp32 (96KB)
    u64   red[3][8][8][16];      // warp-reduced partials [m][ksg][bq][rp*4+bi] (24KB)
    __nv_bfloat16 acth[3][HB][BATCH];   // staged bf16 act planes (1.5KB)
    float wb[3][HB];
    float br[HB], bi[HB], tb[HB];
};

__global__ void __launch_bounds__(BLOCK_R, 1) rec_kernel(
    const float* __restrict__ Wt_w,
    const float* __restrict__ Wr_b, const float* __restrict__ Wi_b,
    const float* __restrict__ Wt_b, const float* __restrict__ b_real,
    const float* __restrict__ b_imag, const float* __restrict__ tau_bias) {
    extern __shared__ char smem_raw[];
    RecSmem& sm = *reinterpret_cast<RecSmem*>(smem_raw);
    const int tid = threadIdx.x;
    const int hbase = blockIdx.x * HB;

    // ---- load weights into SMEM [mat][k][row] (resident for all 512 steps) ----
    for (int idx = tid; idx < 3 * HB * H; idx += BLOCK_R) {
        int m   = idx >> 13;
        int rem = idx & 8191;
        int r   = rem >> 10;
        int k   = rem & 1023;
        float w;
        if (m == 0)      w = g_Wr[(long)(hbase + r) * H + k];
        else if (m == 1) w = g_Wi[(long)(hbase + r) * H + k];
        else             w = Wt_w[(long)(hbase + r) * H + k];
        sm.W[m][k][r] = w;
    }
    if (tid < HB) {
        sm.wb[0][tid] = Wr_b[hbase + tid];
        sm.wb[1][tid] = Wi_b[hbase + tid];
        sm.wb[2][tid] = Wt_b[hbase + tid];
        sm.br[tid] = b_real[hbase + tid];
        sm.bi[tid] = b_imag[hbase + tid];
        sm.tb[tid] = tau_bias[hbase + tid];
    }
    __syncthreads();

    const int m  = tid >> 8;          // 0..2
    const int r5 = tid & 255;
    const int ks = r5 >> 3;           // 0..31
    const int bq = r5 & 7;            // 0..7

    const char* wk_base = (const char*)&sm.W[m][0][0];

    // cell state held in registers for the whole sequence (CTA-private)
    const int cb  = tid >> 3;         // batch (valid when tid < 256)
    const int chl = tid & 7;          // local h
    const int jf  = ((chl >> 1) * 4 + (cb & 3)) * 2 + (chl & 1); // float idx in red block
    const int bq2 = cb >> 2;
    float zr = 0.0f, zi = 0.0f;

    int cur = 0;
    for (int t = 0; t < T_STEPS; t++) {
        // prefetch Ux for the epilogue (overlaps with matmul)
        float ux = 0.0f;
        if (tid < HB * BATCH)
            ux = __ldg(&g_Ux[((long)t * BATCH + cb) * H + hbase + chl]);

        const __nv_bfloat16* actp =
            g_act + (size_t)(cur * 3 + m) * (H * BATCH) + bq * 4;

        u64 acc[16];
#pragma unroll
        for (int j = 0; j < 16; j++) acc[j] = 0ull;

        // software-pipelined act loads (prefetch depth 1)
        uint2 araw = __ldg((const uint2*)(actp + ks * BATCH));
#pragma unroll 4
        for (int i = 0; i < 32; i++) {
            int k = ks + (i << 5);
            uint2 acur = araw;
            if (i < 31)
                araw = __ldg((const uint2*)(actp + (k + 32) * BATCH));
            ulonglong2 wA = *(const ulonglong2*)(wk_base + (size_t)k * (HB * 4));
            ulonglong2 wB = *(const ulonglong2*)(wk_base + (size_t)k * (HB * 4) + 16);
            u64 ad0 = dup2u(bf_lo(acur.x));
            u64 ad1 = dup2u(bf_hi(acur.x));
            u64 ad2 = dup2u(bf_lo(acur.y));
            u64 ad3 = dup2u(bf_hi(acur.y));
            acc[0]  = fma2(ad0, wA.x, acc[0]);
            acc[1]  = fma2(ad1, wA.x, acc[1]);
            acc[2]  = fma2(ad2, wA.x, acc[2]);
            acc[3]  = fma2(ad3, wA.x, acc[3]);
            acc[4]  = fma2(ad0, wA.y, acc[4]);
            acc[5]  = fma2(ad1, wA.y, acc[5]);
            acc[6]  = fma2(ad2, wA.y, acc[6]);
            acc[7]  = fma2(ad3, wA.y, acc[7]);
            acc[8]  = fma2(ad0, wB.x, acc[8]);
            acc[9]  = fma2(ad1, wB.x, acc[9]);
            acc[10] = fma2(ad2, wB.x, acc[10]);
            acc[11] = fma2(ad3, wB.x, acc[11]);
            acc[12] = fma2(ad0, wB.y, acc[12]);
            acc[13] = fma2(ad1, wB.y, acc[13]);
            acc[14] = fma2(ad2, wB.y, acc[14]);
            acc[15] = fma2(ad3, wB.y, acc[15]);
        }

        // warp butterfly over the 4 kq lanes
#pragma unroll
        for (int j = 0; j < 16; j++) {
            u64 o = __shfl_xor_sync(0xffffffffu, acc[j], 8);
            acc[j] = add2(acc[j], o);
            o = __shfl_xor_sync(0xffffffffu, acc[j], 16);
            acc[j] = add2(acc[j], o);
        }
        if ((ks & 3) == 0) {
            int ksg = ks >> 2;
#pragma unroll
            for (int j = 0; j < 16; j++) sm.red[m][ksg][bq][j] = acc[j];
        }
        __syncthreads();

        // elementwise update: reduce 8 k-groups directly from red, then epilogue
        if (tid < HB * BATCH) {
            int b  = cb;
            int hl = chl;
            int h  = hbase + hl;
            float s0 = 0.0f, s1 = 0.0f, s2 = 0.0f;
#pragma unroll
            for (int g = 0; g < 8; g++) {
                s0 += ((const float*)&sm.red[0][g][bq2][0])[jf];
                s1 += ((const float*)&sm.red[1][g][bq2][0])[jf];
                s2 += ((const float*)&sm.red[2][g][bq2][0])[jf];
            }
            float wr = s0 + sm.wb[0][hl];
            float wi = s1 + sm.wb[1][hl];
            float wt = s2 + sm.wb[2][hl];
            float dr = -zr + wr + ux + sm.br[hl];
            float di = -zi + wi + ux + sm.bi[hl];
            float tau = sigmoid_fast(wt) + sm.tb[hl];
            tau = fminf(fmaxf(tau, 0.01f), 1.0f) + 1e-6f;
            float rtau = __fdividef(1.0f, tau);
            dr = fminf(fmaxf(dr * rtau, -10.0f), 10.0f);
            di = fminf(fmaxf(di * rtau, -10.0f), 10.0f);
            zr = fminf(fmaxf(zr + DT_C * dr, -100.0f), 100.0f);
            zi = fminf(fmaxf(zi + DT_C * di, -100.0f), 100.0f);
            g_ZR[((long)t * BATCH + b) * H + h] = zr;
            sm.acth[0][hl][b] = __float2bfloat16(tanh_fast(zr));
            sm.acth[1][hl][b] = __float2bfloat16(tanh_fast(zi));
            sm.acth[2][hl][b] = __float2bfloat16(sqrtf(zr * zr + zi * zi));
        }
        __syncthreads();

        // coalesced store of the 3 bf16 act planes (96 x STG.128)
        const int nxt = cur ^ 1;
        if (tid < 96) {
            int p   = tid >> 5;
            int off = (tid & 31) * 16;  // bytes
            float4 v = *(float4*)((const char*)&sm.acth[p][0][0] + off);
            *(float4*)((char*)(g_act + ((size_t)(nxt * 3 + p) * H + hbase) * BATCH) + off) = v;
        }

        grid_barrier();
        cur ^= 1;
    }
}

// ---------------- launch ----------------
extern "C" void kernel_launch(void* const* d_in, const int* in_sizes, int n_in,
                              void* d_out, int out_size) {
    const float* x_seq    = (const float*)d_in[0];
    const float* Wr_w     = (const float*)d_in[1];
    const float* Wr_b     = (const float*)d_in[2];
    const float* Wi_w     = (const float*)d_in[3];
    const float* Wi_b     = (const float*)d_in[4];
    const float* U_w      = (const float*)d_in[5];
    const float* U_b      = (const float*)d_in[6];
    const float* Wt_w     = (const float*)d_in[7];
    const float* Wt_b     = (const float*)d_in[8];
    const float* b_real   = (const float*)d_in[9];
    const float* b_imag   = (const float*)d_in[10];
    const float* mask_r   = (const float*)d_in[11];
    const float* mask_i   = (const float*)d_in[12];
    const float* tau_bias = (const float*)d_in[13];
    const float* out_w    = (const float*)d_in[14];
    const float* out_b    = (const float*)d_in[15];
    float* y = (float*)d_out;

    float *p_Ux = nullptr, *p_ZR = nullptr;
    cudaGetSymbolAddress((void**)&p_Ux, g_Ux);
    cudaGetSymbolAddress((void**)&p_ZR, g_ZR);

    prep_kernel<<<(H * H + 255) / 256, 256>>>(Wr_w, mask_r, Wi_w, mask_i);
    init_kernel<<<(2 * 3 * H * BATCH + 255) / 256, 256>>>();

    {
        dim3 grid(H / GBN, (T_STEPS * BATCH) / GBM);
        sgemm_abt<<<grid, 256>>>(x_seq, U_w, U_b, p_Ux, T_STEPS * BATCH, H, DIN);
    }

    {
        int smem = (int)sizeof(RecSmem);
        cudaFuncSetAttribute(rec_kernel, cudaFuncAttributeMaxDynamicSharedMemorySize, smem);
        rec_kernel<<<GRID_R, BLOCK_R, smem>>>(Wt_w, Wr_b, Wi_b, Wt_b, b_real, b_imag, tau_bias);
    }

    {
        dim3 grid(H / GBN, (T_STEPS * BATCH) / GBM);
        sgemm_abt<<<grid, 256>>>(p_ZR, out_w, out_b, y, T_STEPS * BATCH, H, H);
    }
}

// round 15
// speedup vs baseline: 1.3777x; 1.2161x over previous
#include <cuda_runtime.h>
#include <cuda_bf16.h>
#include <cuda_fp16.h>
#include <mma.h>
#include <cstdint>
#include <math.h>

using namespace nvcuda;

#define H       1024
#define DIN     512
#define T_STEPS 512
#define BATCH   32
#define DT_C    0.1f

#define GRID_R  128
#define BLOCK_R 768
#define HB      8      // H / GRID_R

typedef unsigned long long u64;

// ---------------- f32x2 packed math (Blackwell) ----------------
__device__ __forceinline__ u64 fma2(u64 a, u64 b, u64 c) {
    u64 d;
    asm("fma.rn.f32x2 %0, %1, %2, %3;" : "=l"(d) : "l"(a), "l"(b), "l"(c));
    return d;
}
__device__ __forceinline__ u64 add2(u64 a, u64 b) {
    u64 d;
    asm("add.rn.f32x2 %0, %1, %2;" : "=l"(d) : "l"(a), "l"(b));
    return d;
}
__device__ __forceinline__ u64 dup2u(unsigned a) {
    u64 d;
    asm("mov.b64 %0, {%1, %1};" : "=l"(d) : "r"(a));
    return d;
}
// bf16 pair decode: u32 (two bf16) -> two f32 bit patterns via PRMT (exact)
__device__ __forceinline__ unsigned bf_lo(unsigned x) {
    unsigned r;
    asm("prmt.b32 %0, %1, %2, 0x1044;" : "=r"(r) : "r"(x), "r"(0u));
    return r;
}
__device__ __forceinline__ unsigned bf_hi(unsigned x) {
    unsigned r;
    asm("prmt.b32 %0, %1, %2, 0x3244;" : "=r"(r) : "r"(x), "r"(0u));
    return r;
}
__device__ __forceinline__ float tanh_fast(float x) {
    float e = __expf(2.0f * x);
    return 1.0f - __fdividef(2.0f, e + 1.0f);
}
__device__ __forceinline__ float sigmoid_fast(float x) {
    return __fdividef(1.0f, 1.0f + __expf(-x));
}

// ---------------- device scratch (static, allocation-free) ----------------
__device__ float g_Wr[H * H];
__device__ float g_Wi[H * H];
__device__ float g_Ux[T_STEPS * BATCH * H];
__device__ __half g_ZRh[T_STEPS * BATCH * H];        // fp16 zr history (GEMM A)
__device__ __half g_xh[T_STEPS * BATCH * DIN];       // fp16 x_seq
__device__ __half g_Uwh[H * DIN];                    // fp16 U_w
__device__ __half g_owh[H * H];                      // fp16 out_w
__device__ __nv_bfloat16 g_act[2 * 3 * H * BATCH];   // [buf][mat][k][b], bf16
__device__ unsigned g_bar_count;
__device__ unsigned g_bar_gen;

// ---------------- grid-wide barrier (all CTAs resident) ----------------
__device__ __forceinline__ void grid_barrier() {
    __syncthreads();
    if (threadIdx.x == 0) {
        unsigned gen = *(volatile unsigned*)&g_bar_gen;
        __threadfence();
        unsigned t = atomicAdd(&g_bar_count, 1u);
        if (t == GRID_R - 1) {
            g_bar_count = 0u;
            __threadfence();
            atomicAdd(&g_bar_gen, 1u);
        } else {
            while (*(volatile unsigned*)&g_bar_gen == gen) { }
        }
        __threadfence();
    }
    __syncthreads();
}

// ---------------- prep kernels ----------------
__global__ void prep_kernel(const float* __restrict__ Wr_w, const float* __restrict__ mask_r,
                            const float* __restrict__ Wi_w, const float* __restrict__ mask_i) {
    int i = blockIdx.x * blockDim.x + threadIdx.x;
    if (i < H * H) {
        g_Wr[i] = Wr_w[i] * (1.0f / (1.0f + expf(-mask_r[i])));
        g_Wi[i] = Wi_w[i] * (1.0f / (1.0f + expf(-mask_i[i])));
    }
}

__global__ void init_kernel() {
    int i = blockIdx.x * blockDim.x + threadIdx.x;
    if (i < 2 * 3 * H * BATCH) g_act[i] = __float2bfloat16(0.0f);
}

__global__ void cvt_half_kernel(const float* __restrict__ s, __half* __restrict__ d, int n) {
    int i = blockIdx.x * blockDim.x + threadIdx.x;
    if (i < n) d[i] = __float2half(s[i]);
}

// ---------------- fp16 HMMA GEMM (wmma): C[MxN] = A[MxK] @ B[NxK]^T + bias ----------------
// CTA tile 128x64, 8 warps (4x2), warp tile 32x32 (2x2 wmma 16x16x16 frags), K-chunk 32.
#define WG_TM 128
#define WG_TN 64
#define WG_TK 32
#define WG_PAD 8

__global__ __launch_bounds__(256) void hgemm_wmma(
    const __half* __restrict__ A, const __half* __restrict__ Bm,
    const float* __restrict__ bias, float* __restrict__ C,
    int M, int N, int K) {
    __shared__ __half As[WG_TM][WG_TK + WG_PAD];
    __shared__ __half Bs[WG_TN][WG_TK + WG_PAD];
    __shared__ float  Cs[WG_TM][WG_TN];

    const int tid = threadIdx.x;
    const int wid = tid >> 5;
    const int bm = blockIdx.y * WG_TM;
    const int bn = blockIdx.x * WG_TN;
    const int wr = wid >> 1;   // 0..3
    const int wc = wid & 1;    // 0..1

    wmma::fragment<wmma::accumulator, 16, 16, 16, float> acc[2][2];
#pragma unroll
    for (int i = 0; i < 2; i++)
#pragma unroll
        for (int j = 0; j < 2; j++) wmma::fill_fragment(acc[i][j], 0.0f);

    for (int k0 = 0; k0 < K; k0 += WG_TK) {
        // A chunk: 128 x 32 halves -> 512 uint4, 2 per thread
#pragma unroll
        for (int i = tid; i < WG_TM * WG_TK / 8; i += 256) {
            int r = i >> 2;
            int c = (i & 3) * 8;
            *(uint4*)&As[r][c] = *(const uint4*)(A + (size_t)(bm + r) * K + k0 + c);
        }
        // B chunk: 64 x 32 halves -> 256 uint4, 1 per thread
#pragma unroll
        for (int i = tid; i < WG_TN * WG_TK / 8; i += 256) {
            int r = i >> 2;
            int c = (i & 3) * 8;
            *(uint4*)&Bs[r][c] = *(const uint4*)(Bm + (size_t)(bn + r) * K + k0 + c);
        }
        __syncthreads();

#pragma unroll
        for (int kk = 0; kk < WG_TK; kk += 16) {
            wmma::fragment<wmma::matrix_a, 16, 16, 16, __half, wmma::row_major> af[2];
            wmma::fragment<wmma::matrix_b, 16, 16, 16, __half, wmma::col_major> bf[2];
#pragma unroll
            for (int i = 0; i < 2; i++)
                wmma::load_matrix_sync(af[i], &As[wr * 32 + i * 16][kk], WG_TK + WG_PAD);
#pragma unroll
            for (int j = 0; j < 2; j++)
                wmma::load_matrix_sync(bf[j], &Bs[wc * 32 + j * 16][kk], WG_TK + WG_PAD);
#pragma unroll
            for (int i = 0; i < 2; i++)
#pragma unroll
                for (int j = 0; j < 2; j++)
                    wmma::mma_sync(acc[i][j], af[i], bf[j], acc[i][j]);
        }
        __syncthreads();
    }

    // stage accumulators in SMEM, then bias + coalesced writeout
#pragma unroll
    for (int i = 0; i < 2; i++)
#pragma unroll
        for (int j = 0; j < 2; j++)
            wmma::store_matrix_sync(&Cs[wr * 32 + i * 16][wc * 32 + j * 16],
                                    acc[i][j], WG_TN, wmma::mem_row_major);
    __syncthreads();

#pragma unroll
    for (int i = tid; i < WG_TM * WG_TN / 4; i += 256) {
        int r = i >> 4;
        int c = (i & 15) * 4;
        float4 v = *(float4*)&Cs[r][c];
        float4 b4 = *(const float4*)(bias + bn + c);
        v.x += b4.x; v.y += b4.y; v.z += b4.z; v.w += b4.w;
        *(float4*)&C[(size_t)(bm + r) * N + bn + c] = v;
    }
}

// ---------------- persistent recurrence kernel (R12, ZR stored fp16) ----------------
struct RecSmem {
    float W[3][H][HB];           // [mat][k][row], fp32 (96KB)
    u64   red[3][8][8][16];      // warp-reduced partials (24KB)
    __nv_bfloat16 acth[3][HB][BATCH];
    float wb[3][HB];
    float br[HB], bi[HB], tb[HB];
};

__global__ void __launch_bounds__(BLOCK_R, 1) rec_kernel(
    const float* __restrict__ Wt_w,
    const float* __restrict__ Wr_b, const float* __restrict__ Wi_b,
    const float* __restrict__ Wt_b, const float* __restrict__ b_real,
    const float* __restrict__ b_imag, const float* __restrict__ tau_bias) {
    extern __shared__ char smem_raw[];
    RecSmem& sm = *reinterpret_cast<RecSmem*>(smem_raw);
    const int tid = threadIdx.x;
    const int hbase = blockIdx.x * HB;

    for (int idx = tid; idx < 3 * HB * H; idx += BLOCK_R) {
        int m   = idx >> 13;
        int rem = idx & 8191;
        int r   = rem >> 10;
        int k   = rem & 1023;
        float w;
        if (m == 0)      w = g_Wr[(long)(hbase + r) * H + k];
        else if (m == 1) w = g_Wi[(long)(hbase + r) * H + k];
        else             w = Wt_w[(long)(hbase + r) * H + k];
        sm.W[m][k][r] = w;
    }
    if (tid < HB) {
        sm.wb[0][tid] = Wr_b[hbase + tid];
        sm.wb[1][tid] = Wi_b[hbase + tid];
        sm.wb[2][tid] = Wt_b[hbase + tid];
        sm.br[tid] = b_real[hbase + tid];
        sm.bi[tid] = b_imag[hbase + tid];
        sm.tb[tid] = tau_bias[hbase + tid];
    }
    __syncthreads();

    const int m  = tid >> 8;
    const int r5 = tid & 255;
    const int ks = r5 >> 3;
    const int bq = r5 & 7;

    const char* wk_base = (const char*)&sm.W[m][0][0];

    const int cb  = tid >> 3;
    const int chl = tid & 7;
    const int jf  = ((chl >> 1) * 4 + (cb & 3)) * 2 + (chl & 1);
    const int bq2 = cb >> 2;
    float zr = 0.0f, zi = 0.0f;

    int cur = 0;
    for (int t = 0; t < T_STEPS; t++) {
        float ux = 0.0f;
        if (tid < HB * BATCH)
            ux = __ldg(&g_Ux[((long)t * BATCH + cb) * H + hbase + chl]);

        const __nv_bfloat16* actp =
            g_act + (size_t)(cur * 3 + m) * (H * BATCH) + bq * 4;

        u64 acc[16];
#pragma unroll
        for (int j = 0; j < 16; j++) acc[j] = 0ull;

        uint2 araw = __ldg((const uint2*)(actp + ks * BATCH));
#pragma unroll 4
        for (int i = 0; i < 32; i++) {
            int k = ks + (i << 5);
            uint2 acur = araw;
            if (i < 31)
                araw = __ldg((const uint2*)(actp + (k + 32) * BATCH));
            ulonglong2 wA = *(const ulonglong2*)(wk_base + (size_t)k * (HB * 4));
            ulonglong2 wB = *(const ulonglong2*)(wk_base + (size_t)k * (HB * 4) + 16);
            u64 ad0 = dup2u(bf_lo(acur.x));
            u64 ad1 = dup2u(bf_hi(acur.x));
            u64 ad2 = dup2u(bf_lo(acur.y));
            u64 ad3 = dup2u(bf_hi(acur.y));
            acc[0]  = fma2(ad0, wA.x, acc[0]);
            acc[1]  = fma2(ad1, wA.x, acc[1]);
            acc[2]  = fma2(ad2, wA.x, acc[2]);
            acc[3]  = fma2(ad3, wA.x, acc[3]);
            acc[4]  = fma2(ad0, wA.y, acc[4]);
            acc[5]  = fma2(ad1, wA.y, acc[5]);
            acc[6]  = fma2(ad2, wA.y, acc[6]);
            acc[7]  = fma2(ad3, wA.y, acc[7]);
            acc[8]  = fma2(ad0, wB.x, acc[8]);
            acc[9]  = fma2(ad1, wB.x, acc[9]);
            acc[10] = fma2(ad2, wB.x, acc[10]);
            acc[11] = fma2(ad3, wB.x, acc[11]);
            acc[12] = fma2(ad0, wB.y, acc[12]);
            acc[13] = fma2(ad1, wB.y, acc[13]);
            acc[14] = fma2(ad2, wB.y, acc[14]);
            acc[15] = fma2(ad3, wB.y, acc[15]);
        }

#pragma unroll
        for (int j = 0; j < 16; j++) {
            u64 o = __shfl_xor_sync(0xffffffffu, acc[j], 8);
            acc[j] = add2(acc[j], o);
            o = __shfl_xor_sync(0xffffffffu, acc[j], 16);
            acc[j] = add2(acc[j], o);
        }
        if ((ks & 3) == 0) {
            int ksg = ks >> 2;
#pragma unroll
            for (int j = 0; j < 16; j++) sm.red[m][ksg][bq][j] = acc[j];
        }
        __syncthreads();

        if (tid < HB * BATCH) {
            int b  = cb;
            int hl = chl;
            int h  = hbase + hl;
            float s0 = 0.0f, s1 = 0.0f, s2 = 0.0f;
#pragma unroll
            for (int g = 0; g < 8; g++) {
                s0 += ((const float*)&sm.red[0][g][bq2][0])[jf];
                s1 += ((const float*)&sm.red[1][g][bq2][0])[jf];
                s2 += ((const float*)&sm.red[2][g][bq2][0])[jf];
            }
            float wr = s0 + sm.wb[0][hl];
            float wi = s1 + sm.wb[1][hl];
            float wt = s2 + sm.wb[2][hl];
            float dr = -zr + wr + ux + sm.br[hl];
            float di = -zi + wi + ux + sm.bi[hl];
            float tau = sigmoid_fast(wt) + sm.tb[hl];
            tau = fminf(fmaxf(tau, 0.01f), 1.0f) + 1e-6f;
            float rtau = __fdividef(1.0f, tau);
            dr = fminf(fmaxf(dr * rtau, -10.0f), 10.0f);
            di = fminf(fmaxf(di * rtau, -10.0f), 10.0f);
            zr = fminf(fmaxf(zr + DT_C * dr, -100.0f), 100.0f);
            zi = fminf(fmaxf(zi + DT_C * di, -100.0f), 100.0f);
            g_ZRh[((long)t * BATCH + b) * H + h] = __float2half(zr);
            sm.acth[0][hl][b] = __float2bfloat16(tanh_fast(zr));
            sm.acth[1][hl][b] = __float2bfloat16(tanh_fast(zi));
            sm.acth[2][hl][b] = __float2bfloat16(sqrtf(zr * zr + zi * zi));
        }
        __syncthreads();

        const int nxt = cur ^ 1;
        if (tid < 96) {
            int p   = tid >> 5;
            int off = (tid & 31) * 16;
            float4 v = *(float4*)((const char*)&sm.acth[p][0][0] + off);
            *(float4*)((char*)(g_act + ((size_t)(nxt * 3 + p) * H + hbase) * BATCH) + off) = v;
        }

        grid_barrier();
        cur ^= 1;
    }
}

// ---------------- launch ----------------
extern "C" void kernel_launch(void* const* d_in, const int* in_sizes, int n_in,
                              void* d_out, int out_size) {
    const float* x_seq    = (const float*)d_in[0];
    const float* Wr_w     = (const float*)d_in[1];
    const float* Wr_b     = (const float*)d_in[2];
    const float* Wi_w     = (const float*)d_in[3];
    const float* Wi_b     = (const float*)d_in[4];
    const float* U_w      = (const float*)d_in[5];
    const float* U_b      = (const float*)d_in[6];
    const float* Wt_w     = (const float*)d_in[7];
    const float* Wt_b     = (const float*)d_in[8];
    const float* b_real   = (const float*)d_in[9];
    const float* b_imag   = (const float*)d_in[10];
    const float* mask_r   = (const float*)d_in[11];
    const float* mask_i   = (const float*)d_in[12];
    const float* tau_bias = (const float*)d_in[13];
    const float* out_w    = (const float*)d_in[14];
    const float* out_b    = (const float*)d_in[15];
    float* y = (float*)d_out;

    float* p_Ux = nullptr;
    __half *p_xh = nullptr, *p_Uwh = nullptr, *p_owh = nullptr, *p_ZRh = nullptr;
    cudaGetSymbolAddress((void**)&p_Ux, g_Ux);
    cudaGetSymbolAddress((void**)&p_xh, g_xh);
    cudaGetSymbolAddress((void**)&p_Uwh, g_Uwh);
    cudaGetSymbolAddress((void**)&p_owh, g_owh);
    cudaGetSymbolAddress((void**)&p_ZRh, g_ZRh);

    prep_kernel<<<(H * H + 255) / 256, 256>>>(Wr_w, mask_r, Wi_w, mask_i);
    init_kernel<<<(2 * 3 * H * BATCH + 255) / 256, 256>>>();

    // fp16 conversions for HMMA GEMMs
    cvt_half_kernel<<<(T_STEPS * BATCH * DIN + 255) / 256, 256>>>(x_seq, p_xh, T_STEPS * BATCH * DIN);
    cvt_half_kernel<<<(H * DIN + 255) / 256, 256>>>(U_w, p_Uwh, H * DIN);
    cvt_half_kernel<<<(H * H + 255) / 256, 256>>>(out_w, p_owh, H * H);

    // Ux = x @ U_w^T + U_b  (M=16384, N=1024, K=512) on HMMA
    {
        dim3 grid(H / WG_TN, (T_STEPS * BATCH) / WG_TM);
        hgemm_wmma<<<grid, 256>>>(p_xh, p_Uwh, U_b, p_Ux, T_STEPS * BATCH, H, DIN);
    }

    // persistent recurrence
    {
        int smem = (int)sizeof(RecSmem);
        cudaFuncSetAttribute(rec_kernel, cudaFuncAttributeMaxDynamicSharedMemorySize, smem);
        rec_kernel<<<GRID_R, BLOCK_R, smem>>>(Wt_w, Wr_b, Wi_b, Wt_b, b_real, b_imag, tau_bias);
    }

    // y = ZR @ out_w^T + out_b  (M=16384, N=1024, K=1024) on HMMA
    {
        dim3 grid(H / WG_TN, (T_STEPS * BATCH) / WG_TM);
        hgemm_wmma<<<grid, 256>>>(p_ZRh, p_owh, out_b, y, T_STEPS * BATCH, H, H);
    }
}